// round 16
// baseline (speedup 1.0000x reference)
#include <cuda_runtime.h>
#include <mma.h>

using namespace nvcuda;

#define NN 100000
#define EE 600000
#define IND 12
#define HD  128
#define NL  3
#define BNEPS 1e-5f
#define SCB 1024
#define NSCAN ((NN + SCB - 1) / SCB)   // 98

// ---------------- device scratch (static, no allocation) ----------------
// GB300 fabric-init (802) flake rate grows with static size: keep minimal.
// src/dst alias into g_buf1 (dead until gemm12); cursor aliases into
// g_buf0 past the msg12 region (dead until gather12).
__device__ float g_buf0[NN * HD];
__device__ float g_buf1[NN * HD];
__device__ int   g_adj[EE];
__device__ int   g_rowptr[NN + 1];
__device__ int   g_deg[NN];
__device__ float g_invdeg[NN];
__device__ int   g_bsum[NSCAN];
__device__ float g_W1c[IND * HD];
__device__ float g_W2c[IND * HD];
__device__ float g_bias1[HD];
__device__ float g_biasd[HD];
__device__ float g_sum[HD];
__device__ float g_sqsum[HD];
__device__ float g_bnsc[2][HD];
__device__ float g_bnsh[2][HD];

__device__ __forceinline__ float* selbuf(int s) { return s ? g_buf1 : g_buf0; }
__device__ __forceinline__ int* srcp() { return (int*)g_buf1; }
__device__ __forceinline__ int* dstp() { return ((int*)g_buf1) + EE; }
__device__ __forceinline__ int* curp() { return (int*)(g_buf0 + (size_t)NN * IND); }

// ---------------- zero pass (deg + folded-weight accumulators) ----------
__global__ void zero_kernel() {
    int i = blockIdx.x * blockDim.x + threadIdx.x;
    if (i < NN) g_deg[i] = 0;
    if (i < IND * HD) { g_W1c[i] = 0.f; g_W2c[i] = 0.f; }
    if (i < HD) { g_bias1[i] = 0.f; g_biasd[i] = 0.f; }
}

// extract edges + inline degree count (per-block dtype detection)
__global__ void extract_count_kernel(const void* p) {
    const int* pi = (const int*)p;
    int nz = (threadIdx.x < 256) ? (pi[2 * threadIdx.x + 1] != 0) : 0;
    nz = __syncthreads_or(nz);      // nz==0 -> int64 layout
    int i = blockIdx.x * blockDim.x + threadIdx.x;
    if (i >= 2 * EE) return;
    int v;
    if (!nz) v = (int)((const long long*)p)[i];
    else     v = pi[i];
    if (i < EE) {
        srcp()[i] = v;
    } else {
        dstp()[i - EE] = v;
        atomicAdd(&g_deg[v], 1);
    }
}

// ---------------- layer-1 folded weights, parallel over K-chunks --------
__global__ void prep_weights_kernel(const float* __restrict__ embW,
                                    const float* __restrict__ emb_b,
                                    const float* __restrict__ Ws,
                                    const float* __restrict__ Wn,
                                    const float* __restrict__ cb) {
    int c = threadIdx.x;
    int k = blockIdx.x;             // 0..12 (12 = bias row)
    int j0 = blockIdx.y * 32;
    const float* v = (k < IND) ? (embW + k * HD) : emb_b;
    float a0 = 0.f, a1 = 0.f, a2 = 0.f, a3 = 0.f;
    float b0 = 0.f, b1v = 0.f, b2v = 0.f, b3 = 0.f;
#pragma unroll
    for (int j = j0; j < j0 + 32; j += 4) {
        float e0 = __ldg(&v[j + 0]), e1 = __ldg(&v[j + 1]);
        float e2 = __ldg(&v[j + 2]), e3 = __ldg(&v[j + 3]);
        a0 += e0 * __ldg(&Ws[(j + 0) * HD + c]);
        a1 += e1 * __ldg(&Ws[(j + 1) * HD + c]);
        a2 += e2 * __ldg(&Ws[(j + 2) * HD + c]);
        a3 += e3 * __ldg(&Ws[(j + 3) * HD + c]);
        b0  += e0 * __ldg(&Wn[(j + 0) * HD + c]);
        b1v += e1 * __ldg(&Wn[(j + 1) * HD + c]);
        b2v += e2 * __ldg(&Wn[(j + 2) * HD + c]);
        b3  += e3 * __ldg(&Wn[(j + 3) * HD + c]);
    }
    float ra = (a0 + a1) + (a2 + a3);
    float rb = (b0 + b1v) + (b2v + b3);
    if (k < IND) {
        atomicAdd(&g_W1c[k * HD + c], ra);
        atomicAdd(&g_W2c[k * HD + c], rb);
    } else {
        atomicAdd(&g_bias1[c], ra + (blockIdx.y == 0 ? __ldg(&cb[c]) : 0.f));
        atomicAdd(&g_biasd[c], rb);
    }
}

// ---------------- parallel CSR scan -------------------------------------
__global__ void blocksum_kernel() {          // <<<NSCAN, SCB>>>
    __shared__ int wsum[32];
    int i = blockIdx.x * SCB + threadIdx.x;
    int v = (i < NN) ? g_deg[i] : 0;
    int lane = threadIdx.x & 31, wid = threadIdx.x >> 5;
#pragma unroll
    for (int off = 16; off; off >>= 1) v += __shfl_down_sync(0xffffffffu, v, off);
    if (lane == 0) wsum[wid] = v;
    __syncthreads();
    if (wid == 0) {
        int t = (lane < 32) ? wsum[lane] : 0;
#pragma unroll
        for (int off = 16; off; off >>= 1) t += __shfl_down_sync(0xffffffffu, t, off);
        if (lane == 0) g_bsum[blockIdx.x] = t;
    }
}
__global__ void scan_bsum_kernel() {         // <<<1, 128>>>  (+BN sum init)
    __shared__ int vals[NSCAN];
    int tid = threadIdx.x;
    if (tid < HD) { g_sum[tid] = 0.f; g_sqsum[tid] = 0.f; }
    if (tid < NSCAN) vals[tid] = g_bsum[tid];
    __syncthreads();
    if (tid == 0) {
        int acc = 0;
        for (int k = 0; k < NSCAN; k++) { int t = vals[k]; vals[k] = acc; acc += t; }
        g_rowptr[NN] = acc;
    }
    __syncthreads();
    if (tid < NSCAN) g_bsum[tid] = vals[tid];
}
__global__ void fill_rowptr_kernel() {       // <<<NSCAN, SCB>>>  (+invdeg)
    __shared__ int wsum[32];
    int i = blockIdx.x * SCB + threadIdx.x;
    int lane = threadIdx.x & 31, wid = threadIdx.x >> 5;
    int v = (i < NN) ? g_deg[i] : 0;
    int inc = v;
#pragma unroll
    for (int off = 1; off < 32; off <<= 1) {
        int t = __shfl_up_sync(0xffffffffu, inc, off);
        if (lane >= off) inc += t;
    }
    if (lane == 31) wsum[wid] = inc;
    __syncthreads();
    if (wid == 0) {
        int wi = wsum[lane];
#pragma unroll
        for (int off = 1; off < 32; off <<= 1) {
            int t = __shfl_up_sync(0xffffffffu, wi, off);
            if (lane >= off) wi += t;
        }
        wsum[lane] = wi;
    }
    __syncthreads();
    int excl = inc - v + (wid ? wsum[wid - 1] : 0) + g_bsum[blockIdx.x];
    if (i < NN) {
        curp()[i] = excl;
        g_rowptr[i] = excl;
        g_invdeg[i] = 1.f / fmaxf((float)v, 1.f);
    }
}

__global__ void place_edges_kernel() {
    int e = blockIdx.x * blockDim.x + threadIdx.x;
    if (e >= EE) return;
    int d = dstp()[e];
    int pos = atomicAdd(&curp()[d], 1);
    g_adj[pos] = srcp()[e];
}

// ---------------- layer-1 gather in 12-dim feature space ---------------
__global__ void gather12_kernel(const float* __restrict__ F) {
    float* __restrict__ msg12 = g_buf0;   // alias
    int gid = blockIdx.x * blockDim.x + threadIdx.x;
    int node = gid >> 2, ch = gid & 3;
    if (node >= NN || ch >= 3) return;
    int beg = __ldg(&g_rowptr[node]);
    int end = __ldg(&g_rowptr[node + 1]);
    float4 acc = make_float4(0.f, 0.f, 0.f, 0.f);
    for (int j = beg; j < end; j++) {
        int s = __ldg(&g_adj[j]);
        float4 v = __ldg((const float4*)(F + (size_t)s * IND) + ch);
        acc.x += v.x; acc.y += v.y; acc.z += v.z; acc.w += v.w;
    }
    float sc = g_invdeg[node];
    acc.x *= sc; acc.y *= sc; acc.z *= sc; acc.w *= sc;
    *(float4*)(msg12 + (size_t)node * IND + ch * 4) = acc;
}

// ---------------- layer-1 GEMM (K=12, fp32 FFMA) -> buf1 raw1 ----------
#define G12NB 8
__global__ void __launch_bounds__(128)
gemm12_kernel(const float* __restrict__ F) {
    const float* __restrict__ msg12 = g_buf0;  // alias
    __shared__ float W1s[IND * HD], W2s[IND * HD];
    __shared__ float Fs[G12NB][IND], Ms[G12NB][IND];
    int c = threadIdx.x;
    for (int i = c; i < IND * HD; i += 128) { W1s[i] = g_W1c[i]; W2s[i] = g_W2c[i]; }
    float bfx = g_bias1[c], bdg = g_biasd[c];
    int nrow_off = c / IND, kk = c % IND;
    float s = 0.f, s2 = 0.f;
    float* C = g_buf1;
    for (int base = blockIdx.x * G12NB; base < NN; base += gridDim.x * G12NB) {
        __syncthreads();
        if (c < 8 * IND) {
            int n = base + nrow_off;
            Fs[nrow_off][kk] = (n < NN) ? __ldg(&F[(size_t)n * IND + kk]) : 0.f;
            Ms[nrow_off][kk] = (n < NN) ? msg12[(size_t)n * IND + kk] : 0.f;
        }
        __syncthreads();
#pragma unroll
        for (int r = 0; r < G12NB; r++) {
            int n = base + r;
            if (n >= NN) break;
            float acc = bfx + (__ldg(&g_deg[n]) ? bdg : 0.f);
#pragma unroll
            for (int k = 0; k < IND; k++)
                acc += Fs[r][k] * W1s[k * HD + c] + Ms[r][k] * W2s[k * HD + c];
            C[(size_t)n * HD + c] = acc;
            s += acc; s2 += acc * acc;
        }
    }
    atomicAdd(&g_sum[c], s);
    atomicAdd(&g_sqsum[c], s2);
}

// ---------------- CSR gather, plain: 8 lanes/node, 16 cols/lane ---------
// 4 nodes per warp -> 2-neighbor unroll x 4 float4 = 8 loads in flight/lane.
__global__ void gather_kernel(int hsel) {
    const float* __restrict__ h = selbuf(hsel);
    float* __restrict__ msg = selbuf(hsel ^ 1);
    int gid = blockIdx.x * blockDim.x + threadIdx.x;
    int node = gid >> 3;
    if (node >= NN) return;
    int sub = gid & 7;
    int beg = __ldg(&g_rowptr[node]);
    int end = __ldg(&g_rowptr[node + 1]);
    float4 A0 = make_float4(0.f, 0.f, 0.f, 0.f), A1 = A0, A2 = A0, A3 = A0;
    int j = beg;
    for (; j + 1 < end; j += 2) {
        int s0 = __ldg(&g_adj[j]);
        int s1 = __ldg(&g_adj[j + 1]);
        const float4* p0 = (const float4*)(h + (size_t)s0 * HD) + sub * 4;
        const float4* p1 = (const float4*)(h + (size_t)s1 * HD) + sub * 4;
        float4 x0 = __ldg(p0 + 0), x1 = __ldg(p0 + 1), x2 = __ldg(p0 + 2), x3 = __ldg(p0 + 3);
        float4 y0 = __ldg(p1 + 0), y1 = __ldg(p1 + 1), y2 = __ldg(p1 + 2), y3 = __ldg(p1 + 3);
        A0.x += x0.x + y0.x; A0.y += x0.y + y0.y; A0.z += x0.z + y0.z; A0.w += x0.w + y0.w;
        A1.x += x1.x + y1.x; A1.y += x1.y + y1.y; A1.z += x1.z + y1.z; A1.w += x1.w + y1.w;
        A2.x += x2.x + y2.x; A2.y += x2.y + y2.y; A2.z += x2.z + y2.z; A2.w += x2.w + y2.w;
        A3.x += x3.x + y3.x; A3.y += x3.y + y3.y; A3.z += x3.z + y3.z; A3.w += x3.w + y3.w;
    }
    if (j < end) {
        int s0 = __ldg(&g_adj[j]);
        const float4* p0 = (const float4*)(h + (size_t)s0 * HD) + sub * 4;
        float4 x0 = __ldg(p0 + 0), x1 = __ldg(p0 + 1), x2 = __ldg(p0 + 2), x3 = __ldg(p0 + 3);
        A0.x += x0.x; A0.y += x0.y; A0.z += x0.z; A0.w += x0.w;
        A1.x += x1.x; A1.y += x1.y; A1.z += x1.z; A1.w += x1.w;
        A2.x += x2.x; A2.y += x2.y; A2.z += x2.z; A2.w += x2.w;
        A3.x += x3.x; A3.y += x3.y; A3.z += x3.z; A3.w += x3.w;
    }
    float sc = g_invdeg[node];
    A0.x *= sc; A0.y *= sc; A0.z *= sc; A0.w *= sc;
    A1.x *= sc; A1.y *= sc; A1.z *= sc; A1.w *= sc;
    A2.x *= sc; A2.y *= sc; A2.z *= sc; A2.w *= sc;
    A3.x *= sc; A3.y *= sc; A3.z *= sc; A3.w *= sc;
    float4* mp = (float4*)(msg + (size_t)node * HD) + sub * 4;
    mp[0] = A0; mp[1] = A1; mp[2] = A2; mp[3] = A3;
}

// ---------------- CSR gather with BN+ReLU: 8 lanes/node ------------------
__global__ void gather_bn_kernel(int hsel, int slot) {
    const float* __restrict__ raw = selbuf(hsel);
    float* __restrict__ msg = selbuf(hsel ^ 1);
    int gid = blockIdx.x * blockDim.x + threadIdx.x;
    int node = gid >> 3;
    if (node >= NN) return;
    int sub = gid & 7;
    int c0 = sub * 16;
    float4 S0 = *(const float4*)&g_bnsc[slot][c0 + 0];
    float4 S1 = *(const float4*)&g_bnsc[slot][c0 + 4];
    float4 S2 = *(const float4*)&g_bnsc[slot][c0 + 8];
    float4 S3 = *(const float4*)&g_bnsc[slot][c0 + 12];
    float4 H0 = *(const float4*)&g_bnsh[slot][c0 + 0];
    float4 H1 = *(const float4*)&g_bnsh[slot][c0 + 4];
    float4 H2 = *(const float4*)&g_bnsh[slot][c0 + 8];
    float4 H3 = *(const float4*)&g_bnsh[slot][c0 + 12];
    int beg = __ldg(&g_rowptr[node]);
    int end = __ldg(&g_rowptr[node + 1]);
    float4 A0 = make_float4(0.f, 0.f, 0.f, 0.f), A1 = A0, A2 = A0, A3 = A0;
    int j = beg;
    for (; j + 1 < end; j += 2) {
        int s0 = __ldg(&g_adj[j]);
        int s1 = __ldg(&g_adj[j + 1]);
        const float4* p0 = (const float4*)(raw + (size_t)s0 * HD) + sub * 4;
        const float4* p1 = (const float4*)(raw + (size_t)s1 * HD) + sub * 4;
        float4 x0 = __ldg(p0 + 0), x1 = __ldg(p0 + 1), x2 = __ldg(p0 + 2), x3 = __ldg(p0 + 3);
        float4 y0 = __ldg(p1 + 0), y1 = __ldg(p1 + 1), y2 = __ldg(p1 + 2), y3 = __ldg(p1 + 3);
        A0.x += fmaxf(x0.x * S0.x + H0.x, 0.f) + fmaxf(y0.x * S0.x + H0.x, 0.f);
        A0.y += fmaxf(x0.y * S0.y + H0.y, 0.f) + fmaxf(y0.y * S0.y + H0.y, 0.f);
        A0.z += fmaxf(x0.z * S0.z + H0.z, 0.f) + fmaxf(y0.z * S0.z + H0.z, 0.f);
        A0.w += fmaxf(x0.w * S0.w + H0.w, 0.f) + fmaxf(y0.w * S0.w + H0.w, 0.f);
        A1.x += fmaxf(x1.x * S1.x + H1.x, 0.f) + fmaxf(y1.x * S1.x + H1.x, 0.f);
        A1.y += fmaxf(x1.y * S1.y + H1.y, 0.f) + fmaxf(y1.y * S1.y + H1.y, 0.f);
        A1.z += fmaxf(x1.z * S1.z + H1.z, 0.f) + fmaxf(y1.z * S1.z + H1.z, 0.f);
        A1.w += fmaxf(x1.w * S1.w + H1.w, 0.f) + fmaxf(y1.w * S1.w + H1.w, 0.f);
        A2.x += fmaxf(x2.x * S2.x + H2.x, 0.f) + fmaxf(y2.x * S2.x + H2.x, 0.f);
        A2.y += fmaxf(x2.y * S2.y + H2.y, 0.f) + fmaxf(y2.y * S2.y + H2.y, 0.f);
        A2.z += fmaxf(x2.z * S2.z + H2.z, 0.f) + fmaxf(y2.z * S2.z + H2.z, 0.f);
        A2.w += fmaxf(x2.w * S2.w + H2.w, 0.f) + fmaxf(y2.w * S2.w + H2.w, 0.f);
        A3.x += fmaxf(x3.x * S3.x + H3.x, 0.f) + fmaxf(y3.x * S3.x + H3.x, 0.f);
        A3.y += fmaxf(x3.y * S3.y + H3.y, 0.f) + fmaxf(y3.y * S3.y + H3.y, 0.f);
        A3.z += fmaxf(x3.z * S3.z + H3.z, 0.f) + fmaxf(y3.z * S3.z + H3.z, 0.f);
        A3.w += fmaxf(x3.w * S3.w + H3.w, 0.f) + fmaxf(y3.w * S3.w + H3.w, 0.f);
    }
    if (j < end) {
        int s0 = __ldg(&g_adj[j]);
        const float4* p0 = (const float4*)(raw + (size_t)s0 * HD) + sub * 4;
        float4 x0 = __ldg(p0 + 0), x1 = __ldg(p0 + 1), x2 = __ldg(p0 + 2), x3 = __ldg(p0 + 3);
        A0.x += fmaxf(x0.x * S0.x + H0.x, 0.f);
        A0.y += fmaxf(x0.y * S0.y + H0.y, 0.f);
        A0.z += fmaxf(x0.z * S0.z + H0.z, 0.f);
        A0.w += fmaxf(x0.w * S0.w + H0.w, 0.f);
        A1.x += fmaxf(x1.x * S1.x + H1.x, 0.f);
        A1.y += fmaxf(x1.y * S1.y + H1.y, 0.f);
        A1.z += fmaxf(x1.z * S1.z + H1.z, 0.f);
        A1.w += fmaxf(x1.w * S1.w + H1.w, 0.f);
        A2.x += fmaxf(x2.x * S2.x + H2.x, 0.f);
        A2.y += fmaxf(x2.y * S2.y + H2.y, 0.f);
        A2.z += fmaxf(x2.z * S2.z + H2.z, 0.f);
        A2.w += fmaxf(x2.w * S2.w + H2.w, 0.f);
        A3.x += fmaxf(x3.x * S3.x + H3.x, 0.f);
        A3.y += fmaxf(x3.y * S3.y + H3.y, 0.f);
        A3.z += fmaxf(x3.z * S3.z + H3.z, 0.f);
        A3.w += fmaxf(x3.w * S3.w + H3.w, 0.f);
    }
    float sc = g_invdeg[node];
    A0.x *= sc; A0.y *= sc; A0.z *= sc; A0.w *= sc;
    A1.x *= sc; A1.y *= sc; A1.z *= sc; A1.w *= sc;
    A2.x *= sc; A2.y *= sc; A2.z *= sc; A2.w *= sc;
    A3.x *= sc; A3.y *= sc; A3.z *= sc; A3.w *= sc;
    float4* mp = (float4*)(msg + (size_t)node * HD) + sub * 4;
    mp[0] = A0; mp[1] = A1; mp[2] = A2; mp[3] = A3;
}

// ---------------- fused dual GEMM (tf32, BK=16, prefetched tiles) -------
#define BM 128
#define BK 16
#define ALD (BK + 4)
#define BLD (HD + 4)
#define WTLD 20
__global__ void __launch_bounds__(256)
gemm_layer_kernel(int hsel, int bnslot,
                  const float* __restrict__ Wsp,
                  const float* __restrict__ Wnp,
                  const float* __restrict__ bias) {
    __shared__ float As[BM * ALD];
    __shared__ float Bs[BK * BLD];
    __shared__ float wtile[8][16 * WTLD];
    __shared__ float colsum[HD], colsq[HD];
    __shared__ float bsc[HD], bsh[HD];

    const float* A1 = selbuf(hsel);
    float* Msg = selbuf(hsel ^ 1);
    float* C = Msg;  // in-place
    const int nrows = NN;
    int tid = threadIdx.x;
    int w = tid >> 5, lane = tid & 31;
    int wm = w & 3, wn = w >> 2;
    int row0 = blockIdx.x * BM;

    if (tid < HD) {
        colsum[tid] = 0.f; colsq[tid] = 0.f;
        if (bnslot >= 0) { bsc[tid] = g_bnsc[bnslot][tid]; bsh[tid] = g_bnsh[bnslot][tid]; }
    }

    int am0 = (tid * 2) >> 2,     ak0 = ((tid * 2) & 3) * 4;
    int am1 = (tid * 2 + 1) >> 2, ak1 = ((tid * 2 + 1) & 3) * 4;
    int arc0 = (row0 + am0) < nrows ? (row0 + am0) : nrows - 1;
    int arc1 = (row0 + am1) < nrows ? (row0 + am1) : nrows - 1;
    int wk0 = (tid * 2) >> 5,     wc0 = ((tid * 2) & 31) * 4;
    int wk1 = (tid * 2 + 1) >> 5, wc1 = ((tid * 2 + 1) & 31) * 4;

    wmma::fragment<wmma::accumulator, 16, 16, 8, float> acc[2][4];
#pragma unroll
    for (int i = 0; i < 2; i++)
#pragma unroll
        for (int j = 0; j < 4; j++) wmma::fill_fragment(acc[i][j], 0.f);

    for (int pass = 0; pass < 2; ++pass) {
        const float* A = pass ? Msg : A1;
        const float* W = pass ? Wnp : Wsp;
        int abn = (pass == 0 && bnslot >= 0);
        for (int k0 = 0; k0 < HD; k0 += BK) {
            float4 va0 = __ldg((const float4*)(A + (size_t)arc0 * HD + k0 + ak0));
            float4 va1 = __ldg((const float4*)(A + (size_t)arc1 * HD + k0 + ak1));
            float4 vw0 = __ldg((const float4*)(W + (size_t)(k0 + wk0) * HD + wc0));
            float4 vw1 = __ldg((const float4*)(W + (size_t)(k0 + wk1) * HD + wc1));
            __syncthreads();
            if (abn) {
                va0.x = fmaxf(va0.x * bsc[k0 + ak0 + 0] + bsh[k0 + ak0 + 0], 0.f);
                va0.y = fmaxf(va0.y * bsc[k0 + ak0 + 1] + bsh[k0 + ak0 + 1], 0.f);
                va0.z = fmaxf(va0.z * bsc[k0 + ak0 + 2] + bsh[k0 + ak0 + 2], 0.f);
                va0.w = fmaxf(va0.w * bsc[k0 + ak0 + 3] + bsh[k0 + ak0 + 3], 0.f);
                va1.x = fmaxf(va1.x * bsc[k0 + ak1 + 0] + bsh[k0 + ak1 + 0], 0.f);
                va1.y = fmaxf(va1.y * bsc[k0 + ak1 + 1] + bsh[k0 + ak1 + 1], 0.f);
                va1.z = fmaxf(va1.z * bsc[k0 + ak1 + 2] + bsh[k0 + ak1 + 2], 0.f);
                va1.w = fmaxf(va1.w * bsc[k0 + ak1 + 3] + bsh[k0 + ak1 + 3], 0.f);
            }
            As[am0 * ALD + ak0 + 0] = wmma::__float_to_tf32(va0.x);
            As[am0 * ALD + ak0 + 1] = wmma::__float_to_tf32(va0.y);
            As[am0 * ALD + ak0 + 2] = wmma::__float_to_tf32(va0.z);
            As[am0 * ALD + ak0 + 3] = wmma::__float_to_tf32(va0.w);
            As[am1 * ALD + ak1 + 0] = wmma::__float_to_tf32(va1.x);
            As[am1 * ALD + ak1 + 1] = wmma::__float_to_tf32(va1.y);
            As[am1 * ALD + ak1 + 2] = wmma::__float_to_tf32(va1.z);
            As[am1 * ALD + ak1 + 3] = wmma::__float_to_tf32(va1.w);
            Bs[wk0 * BLD + wc0 + 0] = wmma::__float_to_tf32(vw0.x);
            Bs[wk0 * BLD + wc0 + 1] = wmma::__float_to_tf32(vw0.y);
            Bs[wk0 * BLD + wc0 + 2] = wmma::__float_to_tf32(vw0.z);
            Bs[wk0 * BLD + wc0 + 3] = wmma::__float_to_tf32(vw0.w);
            Bs[wk1 * BLD + wc1 + 0] = wmma::__float_to_tf32(vw1.x);
            Bs[wk1 * BLD + wc1 + 1] = wmma::__float_to_tf32(vw1.y);
            Bs[wk1 * BLD + wc1 + 2] = wmma::__float_to_tf32(vw1.z);
            Bs[wk1 * BLD + wc1 + 3] = wmma::__float_to_tf32(vw1.w);
            __syncthreads();
#pragma unroll
            for (int ks = 0; ks < BK; ks += 8) {
                wmma::fragment<wmma::matrix_a, 16, 16, 8, wmma::precision::tf32, wmma::row_major> af[2];
                wmma::fragment<wmma::matrix_b, 16, 16, 8, wmma::precision::tf32, wmma::row_major> bf[4];
#pragma unroll
                for (int i = 0; i < 2; i++)
                    wmma::load_matrix_sync(af[i], &As[(wm * 32 + i * 16) * ALD + ks], ALD);
#pragma unroll
                for (int j = 0; j < 4; j++)
                    wmma::load_matrix_sync(bf[j], &Bs[ks * BLD + wn * 64 + j * 16], BLD);
#pragma unroll
                for (int i = 0; i < 2; i++)
#pragma unroll
                    for (int j = 0; j < 4; j++)
                        wmma::mma_sync(acc[i][j], af[i], bf[j], acc[i][j]);
            }
        }
    }

    float* wt = wtile[w];
    int cl = lane & 15;
    int rh = lane >> 4;
#pragma unroll
    for (int i = 0; i < 2; i++) {
#pragma unroll
        for (int j = 0; j < 4; j++) {
            wmma::store_matrix_sync(wt, acc[i][j], WTLD, wmma::mem_row_major);
            __syncwarp();
            int gc = wn * 64 + j * 16 + cl;
            int rbase = row0 + wm * 32 + i * 16 + rh * 8;
            float bia = bias[gc];
            float s = 0.f, s2 = 0.f;
#pragma unroll
            for (int r = 0; r < 8; r++) {
                int gr = rbase + r;
                float v = wt[(rh * 8 + r) * WTLD + cl] + bia;
                if (gr < nrows) {
                    C[(size_t)gr * HD + gc] = v;
                    s += v;
                    s2 += v * v;
                }
            }
            s  += __shfl_down_sync(0xffffffffu, s, 16);
            s2 += __shfl_down_sync(0xffffffffu, s2, 16);
            if (lane < 16) {
                atomicAdd(&colsum[gc], s);
                atomicAdd(&colsq[gc], s2);
            }
            __syncwarp();
        }
    }
    __syncthreads();
    if (tid < HD) {
        atomicAdd(&g_sum[tid], colsum[tid]);
        atomicAdd(&g_sqsum[tid], colsq[tid]);
    }
}

// ---------------- BN finalize into slot (+self-reset) ------------------
__global__ void bn_finalize_kernel(const float* __restrict__ gamma,
                                   const float* __restrict__ beta, int slot) {
    int c = threadIdx.x;
    float mu = g_sum[c] * (1.0f / NN);
    float var = g_sqsum[c] * (1.0f / NN) - mu * mu;
    float r = rsqrtf(var + BNEPS);
    float a = gamma[c] * r;
    g_bnsc[slot][c] = a;
    g_bnsh[slot][c] = beta[c] - mu * a;
    g_sum[c] = 0.f;
    g_sqsum[c] = 0.f;
}

// ---------------- layer-2 act: h2 = relu(bn1(raw2)) + relu(bn0(raw1)) --
__global__ void bn_apply2_kernel() {
    float* X = g_buf0;                // raw2 -> h2 (in place)
    const float* Res = g_buf1;        // raw1
    int i = blockIdx.x * blockDim.x + threadIdx.x;
    int total4 = NN * HD / 4;
    if (i >= total4) return;
    int c = (i & 31) * 4;
    float4 v = ((float4*)X)[i];
    float4 r = ((const float4*)Res)[i];
    v.x = fmaxf(v.x * g_bnsc[1][c+0] + g_bnsh[1][c+0], 0.f) + fmaxf(r.x * g_bnsc[0][c+0] + g_bnsh[0][c+0], 0.f);
    v.y = fmaxf(v.y * g_bnsc[1][c+1] + g_bnsh[1][c+1], 0.f) + fmaxf(r.y * g_bnsc[0][c+1] + g_bnsh[0][c+1], 0.f);
    v.z = fmaxf(v.z * g_bnsc[1][c+2] + g_bnsh[1][c+2], 0.f) + fmaxf(r.z * g_bnsc[0][c+2] + g_bnsh[0][c+2], 0.f);
    v.w = fmaxf(v.w * g_bnsc[1][c+3] + g_bnsh[1][c+3], 0.f) + fmaxf(r.w * g_bnsc[0][c+3] + g_bnsh[0][c+3], 0.f);
    ((float4*)X)[i] = v;
}

// ---------------- tensor-core head ----------------
#define HALD 20
#define HBLD 68
#define HWT  36
__global__ void __launch_bounds__(256)
head_kernel(const float* __restrict__ W1,
            const float* __restrict__ b1,
            const float* __restrict__ W2,
            const float* __restrict__ b2,
            float* __restrict__ out) {
    const float* Raw = g_buf1;        // raw3
    const float* Res = g_buf0;        // h2
    __shared__ float As[BM * HALD];
    __shared__ float Bs[16 * HBLD];
    __shared__ float wt2[8][16 * HWT];
    __shared__ float part[BM][4];
    __shared__ float bsc[HD], bsh[HD];
    __shared__ float b1s[64], w2s[128];

    int tid = threadIdx.x;
    int w = tid >> 5, lane = tid & 31;
    int wm = w & 3, wn = w >> 2;
    int row0 = blockIdx.x * BM;

    if (tid < HD) { bsc[tid] = g_bnsc[0][tid]; bsh[tid] = g_bnsh[0][tid]; }
    if (tid < 64) b1s[tid] = b1[tid];
    if (tid < 128) w2s[tid] = W2[tid];

    int am0 = (tid * 2) >> 2,     ak0 = ((tid * 2) & 3) * 4;
    int am1 = (tid * 2 + 1) >> 2, ak1 = ((tid * 2 + 1) & 3) * 4;
    int arc0 = (row0 + am0) < NN ? (row0 + am0) : NN - 1;
    int arc1 = (row0 + am1) < NN ? (row0 + am1) : NN - 1;
    int wk = tid >> 4, wc = (tid & 15) * 4;

    wmma::fragment<wmma::accumulator, 16, 16, 8, float> acc[2][2];
#pragma unroll
    for (int i = 0; i < 2; i++)
#pragma unroll
        for (int j = 0; j < 2; j++) wmma::fill_fragment(acc[i][j], 0.f);

    for (int k0 = 0; k0 < HD; k0 += 16) {
        float4 va0 = __ldg((const float4*)(Raw + (size_t)arc0 * HD + k0 + ak0));
        float4 vr0 = __ldg((const float4*)(Res + (size_t)arc0 * HD + k0 + ak0));
        float4 va1 = __ldg((const float4*)(Raw + (size_t)arc1 * HD + k0 + ak1));
        float4 vr1 = __ldg((const float4*)(Res + (size_t)arc1 * HD + k0 + ak1));
        float4 vw = __ldg((const float4*)(W1 + (size_t)(k0 + wk) * 64 + wc));
        __syncthreads();
        va0.x = fmaxf(va0.x * bsc[k0 + ak0 + 0] + bsh[k0 + ak0 + 0], 0.f) + vr0.x;
        va0.y = fmaxf(va0.y * bsc[k0 + ak0 + 1] + bsh[k0 + ak0 + 1], 0.f) + vr0.y;
        va0.z = fmaxf(va0.z * bsc[k0 + ak0 + 2] + bsh[k0 + ak0 + 2], 0.f) + vr0.z;
        va0.w = fmaxf(va0.w * bsc[k0 + ak0 + 3] + bsh[k0 + ak0 + 3], 0.f) + vr0.w;
        va1.x = fmaxf(va1.x * bsc[k0 + ak1 + 0] + bsh[k0 + ak1 + 0], 0.f) + vr1.x;
        va1.y = fmaxf(va1.y * bsc[k0 + ak1 + 1] + bsh[k0 + ak1 + 1], 0.f) + vr1.y;
        va1.z = fmaxf(va1.z * bsc[k0 + ak1 + 2] + bsh[k0 + ak1 + 2], 0.f) + vr1.z;
        va1.w = fmaxf(va1.w * bsc[k0 + ak1 + 3] + bsh[k0 + ak1 + 3], 0.f) + vr1.w;
        As[am0 * HALD + ak0 + 0] = wmma::__float_to_tf32(va0.x);
        As[am0 * HALD + ak0 + 1] = wmma::__float_to_tf32(va0.y);
        As[am0 * HALD + ak0 + 2] = wmma::__float_to_tf32(va0.z);
        As[am0 * HALD + ak0 + 3] = wmma::__float_to_tf32(va0.w);
        As[am1 * HALD + ak1 + 0] = wmma::__float_to_tf32(va1.x);
        As[am1 * HALD + ak1 + 1] = wmma::__float_to_tf32(va1.y);
        As[am1 * HALD + ak1 + 2] = wmma::__float_to_tf32(va1.z);
        As[am1 * HALD + ak1 + 3] = wmma::__float_to_tf32(va1.w);
        Bs[wk * HBLD + wc + 0] = wmma::__float_to_tf32(vw.x);
        Bs[wk * HBLD + wc + 1] = wmma::__float_to_tf32(vw.y);
        Bs[wk * HBLD + wc + 2] = wmma::__float_to_tf32(vw.z);
        Bs[wk * HBLD + wc + 3] = wmma::__float_to_tf32(vw.w);
        __syncthreads();
#pragma unroll
        for (int ks = 0; ks < 16; ks += 8) {
            wmma::fragment<wmma::matrix_a, 16, 16, 8, wmma::precision::tf32, wmma::row_major> af[2];
            wmma::fragment<wmma::matrix_b, 16, 16, 8, wmma::precision::tf32, wmma::row_major> bf[2];
#pragma unroll
            for (int i = 0; i < 2; i++)
                wmma::load_matrix_sync(af[i], &As[(wm * 32 + i * 16) * HALD + ks], HALD);
#pragma unroll
            for (int j = 0; j < 2; j++)
                wmma::load_matrix_sync(bf[j], &Bs[ks * HBLD + wn * 32 + j * 16], HBLD);
#pragma unroll
            for (int i = 0; i < 2; i++)
#pragma unroll
                for (int j = 0; j < 2; j++)
                    wmma::mma_sync(acc[i][j], af[i], bf[j], acc[i][j]);
        }
    }

    float* wt = wt2[w];
    int rr = lane >> 1, hh = lane & 1;
#pragma unroll
    for (int i = 0; i < 2; i++) {
        wmma::store_matrix_sync(wt,      acc[i][0], HWT, wmma::mem_row_major);
        wmma::store_matrix_sync(wt + 16, acc[i][1], HWT, wmma::mem_row_major);
        __syncwarp();
        float o0 = 0.f, o1 = 0.f;
#pragma unroll
        for (int c = 0; c < 16; c++) {
            int col = hh * 16 + c;
            int gcol = wn * 32 + col;
            float v = fmaxf(wt[rr * HWT + col] + b1s[gcol], 0.f);
            o0 += v * w2s[gcol * 2 + 0];
            o1 += v * w2s[gcol * 2 + 1];
        }
        o0 += __shfl_xor_sync(0xffffffffu, o0, 1);
        o1 += __shfl_xor_sync(0xffffffffu, o1, 1);
        if (hh == 0) {
            int lr = wm * 32 + i * 16 + rr;
            part[lr][wn * 2 + 0] = o0;
            part[lr][wn * 2 + 1] = o1;
        }
        __syncwarp();
    }
    __syncthreads();
    if (tid < BM) {
        int gr = row0 + tid;
        if (gr < NN) {
            out[gr * 2 + 0] = part[tid][0] + part[tid][2] + b2[0];
            out[gr * 2 + 1] = part[tid][1] + part[tid][3] + b2[1];
        }
    }
}

// ---------------- launch (kernel launches ONLY) ----------------
extern "C" void kernel_launch(void* const* d_in, const int* in_sizes, int n_in,
                              void* d_out, int out_size) {
    const float* features = (const float*)d_in[0];
    const void*  edge     = d_in[1];
    const float* emb_W    = (const float*)d_in[2];
    const float* emb_b    = (const float*)d_in[3];
    const float* Wself    = (const float*)d_in[4];
    const float* Wneigh   = (const float*)d_in[5];
    const float* conv_b   = (const float*)d_in[6];
    const float* gamma    = (const float*)d_in[7];
    const float* beta     = (const float*)d_in[8];
    const float* W1       = (const float*)d_in[9];
    const float* b1       = (const float*)d_in[10];
    const float* W2       = (const float*)d_in[11];
    const float* b2       = (const float*)d_in[12];
    float* out = (float*)d_out;

    zero_kernel<<<(NN + 255) / 256, 256>>>();
    extract_count_kernel<<<(2 * EE + 255) / 256, 256>>>(edge);
    prep_weights_kernel<<<dim3(IND + 1, 4), 128>>>(emb_W, emb_b, Wself, Wneigh, conv_b);
    blocksum_kernel<<<NSCAN, SCB>>>();
    scan_bsum_kernel<<<1, 128>>>();
    fill_rowptr_kernel<<<NSCAN, SCB>>>();
    place_edges_kernel<<<(EE + 255) / 256, 256>>>();

    // ---- layer 1 in 12-dim space ----
    gather12_kernel<<<(NN * 4 + 255) / 256, 256>>>(features);   // msg12 -> buf0 alias
    gemm12_kernel<<<1024, 128>>>(features);                     // -> buf1 raw1 + stats
    bn_finalize_kernel<<<1, HD>>>(gamma, beta, 0);              // BN1 -> slot 0

    // ---- layer 2 (h1 never materialized; BN1 applied on the fly) ----
    gather_bn_kernel<<<(NN * 8 + 255) / 256, 256>>>(1, 0);      // raw1(buf1) -> msg(buf0)
    gemm_layer_kernel<<<(NN + BM - 1) / BM, 256>>>(
        1, 0, Wself + (size_t)1 * HD * HD, Wneigh + (size_t)1 * HD * HD,
        conv_b + 1 * HD);                                        // -> buf0 raw2
    bn_finalize_kernel<<<1, HD>>>(gamma + 1 * HD, beta + 1 * HD, 1);  // BN2 -> slot 1
    bn_apply2_kernel<<<(NN * HD / 4 + 255) / 256, 256>>>();     // buf0 = h2

    // ---- layer 3 ----
    gather_kernel<<<(NN * 8 + 255) / 256, 256>>>(0);            // h2(buf0) -> msg(buf1)
    gemm_layer_kernel<<<(NN + BM - 1) / BM, 256>>>(
        0, -1, Wself + (size_t)2 * HD * HD, Wneigh + (size_t)2 * HD * HD,
        conv_b + 2 * HD);                                        // -> buf1 raw3
    bn_finalize_kernel<<<1, HD>>>(gamma + 2 * HD, beta + 2 * HD, 0);  // BN3 -> slot 0
    head_kernel<<<(NN + BM - 1) / BM, 256>>>(W1, b1, W2, b2, out);   // raw3+h2 -> out
}